// round 2
// baseline (speedup 1.0000x reference)
#include <cuda_runtime.h>
#include <cuda_bf16.h>
#include <cstdint>

// ---------------------------------------------------------------------------
// Problem constants: B=16, R=64, NOBJ=32, SIZE=64
//   sp maps:   (1024, 2, 64, 64) binary rectangle masks
//   conv1:     2->64, 5x5 valid -> (1024,64,60,60), +bias, maxpool2 -> (...,30,30)
//   conv2:     64->32, 5x5 valid -> (1024,32,26,26), +bias, maxpool2 -> 13x13
//   mean(13x13) -> (1024,32);  fc: (1024,32)@(512,32)^T + b, relu -> (1024,512)
// ---------------------------------------------------------------------------

#define NPAIR 1024
#define X1_PER_PAIR (64*30*30)   // 57600

// Scratch (allocation-free rule: __device__ globals)
__device__ float g_P[64*2*36];                      // 6x6 prefix sums of conv1 weights
__device__ float g_x1[(size_t)NPAIR * X1_PER_PAIR]; // pooled conv1 features, ~236 MB
__device__ float g_feat[NPAIR * 32];                // post-mean features

typedef unsigned long long u64;

__device__ __forceinline__ u64 pack2(float lo, float hi) {
    u64 r; asm("mov.b64 %0, {%1, %2};" : "=l"(r) : "f"(lo), "f"(hi)); return r;
}
__device__ __forceinline__ void unpack2(float& lo, float& hi, u64 v) {
    asm("mov.b64 {%0, %1}, %2;" : "=f"(lo), "=f"(hi) : "l"(v));
}
__device__ __forceinline__ void fma2(u64& d, u64 a, u64 b) {
    asm("fma.rn.f32x2 %0, %1, %2, %0;" : "+l"(d) : "l"(a), "l"(b));
}

// ---------------------------------------------------------------------------
// Kernel 1: 2-D exclusive prefix sums of conv1 weights. 128 threads = (co,ci).
// ---------------------------------------------------------------------------
__global__ void k_prefix(const float* __restrict__ conv1_w) {
    int t = threadIdx.x;            // t = co*2 + ci, 0..127
    if (t >= 128) return;
    const float* w = conv1_w + t * 25;
    float P[6][6];
#pragma unroll
    for (int i = 0; i < 6; ++i) { P[0][i] = 0.f; P[i][0] = 0.f; }
#pragma unroll
    for (int j = 1; j <= 5; ++j)
#pragma unroll
        for (int i = 1; i <= 5; ++i)
            P[j][i] = w[(j-1)*5 + (i-1)] + P[j-1][i] + P[j][i-1] - P[j-1][i-1];
#pragma unroll
    for (int j = 0; j < 6; ++j)
#pragma unroll
        for (int i = 0; i < 6; ++i)
            g_P[t*36 + j*6 + i] = P[j][i];
}

// ---------------------------------------------------------------------------
// Kernel 2: rasterize (implicitly) + conv1 + bias + maxpool2, via prefix trick.
// Grid: 1024 blocks (one per pair), 256 threads.
// conv1(co,y,x) = sum_ci rectsum(P[co][ci], window(y,x) ∩ mask-rect(ci))
// ---------------------------------------------------------------------------
__global__ void k_sp_conv1(const float* __restrict__ bboxes,
                           const int*   __restrict__ pairs,
                           const float* __restrict__ conv1_b) {
    __shared__ float sP[4608];            // [co][ci][6][6]
    __shared__ int sxlo[2], sxhi[2], sylo[2], syhi[2];

    int n = blockIdx.x, tid = threadIdx.x;
    for (int i = tid; i < 4608; i += 256) sP[i] = g_P[i];

    if (tid == 0) {
        int b = n >> 6, r = n & 63;
        int o0 = pairs[(b*64 + r)*2 + 0];
        int o1 = pairs[(b*64 + r)*2 + 1];
        const float* A  = bboxes + ((size_t)b*32 + o0)*4;
        const float* Bx = bboxes + ((size_t)b*32 + o1)*4;
        float ux1 = fminf(A[0], Bx[0]), uy1 = fminf(A[1], Bx[1]);
        float ux2 = fmaxf(A[2], Bx[2]), uy2 = fmaxf(A[3], Bx[3]);
        float uw = fmaxf(ux2 - ux1, 1e-6f), uh = fmaxf(uy2 - uy1, 1e-6f);
        const float* bx[2] = {A, Bx};
#pragma unroll
        for (int ci = 0; ci < 2; ++ci) {
            float x1 = (bx[ci][0] - ux1) / uw * 64.0f;
            float y1 = (bx[ci][1] - uy1) / uh * 64.0f;
            float x2 = (bx[ci][2] - ux1) / uw * 64.0f;
            float y2 = (bx[ci][3] - uy1) / uh * 64.0f;
            // pixel-center test: c+0.5 in [v1,v2]  <=>  ceil(v1-0.5) <= c <= floor(v2-0.5)
            sxlo[ci] = max(0,  (int)ceilf (x1 - 0.5f));
            sxhi[ci] = min(63, (int)floorf(x2 - 0.5f));
            sylo[ci] = max(0,  (int)ceilf (y1 - 0.5f));
            syhi[ci] = min(63, (int)floorf(y2 - 0.5f));
        }
    }
    __syncthreads();

    for (int pix = tid; pix < 900; pix += 256) {
        int py = pix / 30, px = pix - py*30;
        int off[4][2][4];
#pragma unroll
        for (int s = 0; s < 4; ++s) {
            int y = 2*py + (s >> 1), x = 2*px + (s & 1);
#pragma unroll
            for (int ci = 0; ci < 2; ++ci) {
                int dxlo = max(0, sxlo[ci] - x), dxhi = min(4, sxhi[ci] - x);
                int dylo = max(0, sylo[ci] - y), dyhi = min(4, syhi[ci] - y);
                bool v = (dxhi >= dxlo) && (dyhi >= dylo);
                int base = ci * 36;
                // invalid -> all offsets 0 -> P0-P0-P0+P0 = 0 (branch-free)
                off[s][ci][0] = v ? base + (dyhi+1)*6 + (dxhi+1) : 0;
                off[s][ci][1] = v ? base + dylo*6     + (dxhi+1) : 0;
                off[s][ci][2] = v ? base + (dyhi+1)*6 + dxlo     : 0;
                off[s][ci][3] = v ? base + dylo*6     + dxlo     : 0;
            }
        }
        float* outp = g_x1 + (size_t)n * X1_PER_PAIR + pix;
#pragma unroll 4
        for (int co = 0; co < 64; ++co) {
            const float* Pc = sP + co * 72;
            float best = -3.4e38f;
#pragma unroll
            for (int s = 0; s < 4; ++s) {
                float v = 0.f;
#pragma unroll
                for (int ci = 0; ci < 2; ++ci) {
                    const int* o = off[s][ci];
                    v += Pc[o[0]] - Pc[o[1]] - Pc[o[2]] + Pc[o[3]];
                }
                best = fmaxf(best, v);
            }
            outp[co * 900] = best + conv1_b[co];
        }
    }
}

// ---------------------------------------------------------------------------
// Kernel 3: conv2 + bias + maxpool2 + spatial mean. One block per pair.
// 338 threads; each thread owns 2 output pixels (y,x) and (y+13,x) packed into
// an f32x2 lane; acc[32] f32x2 accumulators (all 32 output channels).
// Weights pre-packed {w,w} in shared so the inner loop is LDS.64 + FFMA2 only.
// ---------------------------------------------------------------------------
#define CI_CHUNK 16
#define W_ROW 34                                  // u64 row stride (16B aligned, low conflict)
#define SMEM_IN_BYTES   (CI_CHUNK * 900 * 4)      // 57600
#define SMEM_W_BYTES    (CI_CHUNK * 25 * W_ROW * 8) // 108800
#define SMEM3_BYTES     (SMEM_IN_BYTES + SMEM_W_BYTES) // 166400

__global__ void __launch_bounds__(352, 1)
k_conv2(const float* __restrict__ conv2_w, const float* __restrict__ conv2_b) {
    extern __shared__ char smem[];
    float* s_in = (float*)smem;                   // [CI_CHUNK][900]
    u64*   s_w  = (u64*)(smem + SMEM_IN_BYTES);   // [CI_CHUNK*25][W_ROW], {w,w} packed

    int n = blockIdx.x, tid = threadIdx.x;
    int p = tid;                                  // 0..337
    int y0 = p / 26, x0 = p - y0 * 26;            // pixel pair: (y0,x0) and (y0+13,x0)

    u64 acc[32];
#pragma unroll
    for (int co = 0; co < 32; ++co) acc[co] = 0ull;

    const float4* gsrc_base = (const float4*)(g_x1 + (size_t)n * X1_PER_PAIR);

    for (int ci0 = 0; ci0 < 64; ci0 += CI_CHUNK) {
        __syncthreads();
        // load input chunk (contiguous, vectorized)
        const float4* src = gsrc_base + (ci0 * 900) / 4;
        float4* dst = (float4*)s_in;
        for (int i = tid; i < (CI_CHUNK * 900) / 4; i += 338) dst[i] = src[i];
        // load + pre-pack weight chunk: consecutive i -> consecutive k (coalesced gmem)
        for (int i = tid; i < 32 * CI_CHUNK * 25; i += 338) {
            int co  = i / (CI_CHUNK * 25);
            int rem = i - co * (CI_CHUNK * 25);
            int cil = rem / 25;
            int k   = rem - cil * 25;
            float w = conv2_w[co * 1600 + (ci0 + cil) * 25 + k];
            s_w[(cil * 25 + k) * W_ROW + co] = pack2(w, w);
        }
        __syncthreads();

        for (int cil = 0; cil < CI_CHUNK; ++cil) {
            const float* ib = s_in + cil * 900;
            const u64*   wb = s_w + cil * 25 * W_ROW;
#pragma unroll 1
            for (int dy = 0; dy < 5; ++dy) {
                const float* r0 = ib + (y0 + dy) * 30 + x0;
                const float* r1 = r0 + 390;       // +13 rows
#pragma unroll
                for (int dx = 0; dx < 5; ++dx) {
                    u64 in2 = pack2(r0[dx], r1[dx]);
                    const u64* wp = wb + (dy * 5 + dx) * W_ROW;
#pragma unroll
                    for (int co = 0; co < 32; ++co) fma2(acc[co], wp[co], in2);
                }
            }
        }
    }
    __syncthreads();

    // Epilogue: stage conv outputs, maxpool 2x2 (26->13), mean over 169, +bias.
    float* s_out  = (float*)smem;                 // [32][676]
    float* s_pool = (float*)(smem + 32 * 676 * 4); // [32][169]
#pragma unroll
    for (int co = 0; co < 32; ++co) {
        float v0, v1; unpack2(v0, v1, acc[co]);
        s_out[co * 676 + p]       = v0;
        s_out[co * 676 + p + 338] = v1;
    }
    __syncthreads();
    for (int idx = tid; idx < 32 * 169; idx += 338) {
        int co = idx / 169, q = idx - co * 169;
        int qy = q / 13, qx = q - qy * 13;
        const float* o = s_out + co * 676 + qy * 52 + qx * 2;
        s_pool[idx] = fmaxf(fmaxf(o[0], o[1]), fmaxf(o[26], o[27]));
    }
    __syncthreads();
    if (tid < 32) {
        const float* pp = s_pool + tid * 169;
        float s = 0.f;
#pragma unroll 13
        for (int q = 0; q < 169; ++q) s += pp[q];
        g_feat[n * 32 + tid] = s * (1.0f / 169.0f) + conv2_b[tid];
    }
}

// ---------------------------------------------------------------------------
// Kernel 4: fc (32 -> 512) + relu. One block per pair, 512 threads.
// ---------------------------------------------------------------------------
__global__ void k_fc(const float* __restrict__ fc_w, const float* __restrict__ fc_b,
                     float* __restrict__ out) {
    __shared__ float sf[32];
    int n = blockIdx.x, tid = threadIdx.x;
    if (tid < 32) sf[tid] = g_feat[n * 32 + tid];
    __syncthreads();
    float s = fc_b[tid];
    const float* w = fc_w + tid * 32;
#pragma unroll
    for (int k = 0; k < 32; ++k) s += sf[k] * w[k];
    out[(size_t)n * 512 + tid] = fmaxf(s, 0.f);
}

// ---------------------------------------------------------------------------
extern "C" void kernel_launch(void* const* d_in, const int* in_sizes, int n_in,
                              void* d_out, int out_size) {
    const float* bboxes  = (const float*)d_in[0];
    // d_in[1]=num_obj, d_in[2]=num_relation (constant, unused)
    const int*   pairs   = (const int*)  d_in[3];
    const float* conv1_w = (const float*)d_in[4];
    const float* conv1_b = (const float*)d_in[5];
    const float* conv2_w = (const float*)d_in[6];
    const float* conv2_b = (const float*)d_in[7];
    const float* fc_w    = (const float*)d_in[8];
    const float* fc_b    = (const float*)d_in[9];
    float* out = (float*)d_out;

    cudaFuncSetAttribute(k_conv2, cudaFuncAttributeMaxDynamicSharedMemorySize,
                         SMEM3_BYTES);

    k_prefix  <<<1, 128>>>(conv1_w);
    k_sp_conv1<<<NPAIR, 256>>>(bboxes, pairs, conv1_b);
    k_conv2   <<<NPAIR, 338, SMEM3_BYTES>>>(conv2_w, conv2_b);
    k_fc      <<<NPAIR, 512>>>(fc_w, fc_b, out);
}

// round 3
// speedup vs baseline: 1.1358x; 1.1358x over previous
#include <cuda_runtime.h>
#include <cuda_bf16.h>
#include <cstdint>

// ---------------------------------------------------------------------------
// B=16, R=64, NOBJ=32, SIZE=64
//   sp maps: (1024,2,64,64) rectangle indicators (never materialized)
//   conv1(2->64,5x5)+pool2 -> g_x1 (1024,64,30,30)   [prefix-sum trick + class tables]
//   conv2(64->32,5x5)+pool2+mean -> g_feat (1024,32) [f32x2 register-tiled]
//   fc(32->512)+relu -> out (1024,512)
// ---------------------------------------------------------------------------

#define NPAIR 1024
#define X1_PER_PAIR (64*30*30)   // 57600

__device__ float g_P[64*2*36];                       // 6x6 prefix sums of conv1 weights
__device__ float g_x1[(size_t)NPAIR * X1_PER_PAIR];  // pooled conv1 features
__device__ float g_feat[NPAIR * 32];

typedef unsigned long long u64;

__device__ __forceinline__ u64 pack2(float lo, float hi) {
    u64 r; asm("mov.b64 %0, {%1, %2};" : "=l"(r) : "f"(lo), "f"(hi)); return r;
}
__device__ __forceinline__ void unpack2(float& lo, float& hi, u64 v) {
    asm("mov.b64 {%0, %1}, %2;" : "=f"(lo), "=f"(hi) : "l"(v));
}
__device__ __forceinline__ void fma2(u64& d, u64 a, u64 b) {
    asm("fma.rn.f32x2 %0, %1, %2, %0;" : "+l"(d) : "l"(a), "l"(b));
}

// ---------------------------------------------------------------------------
// Kernel 1: 2-D prefix sums of conv1 weights. 128 threads = (co,ci).
// ---------------------------------------------------------------------------
__global__ void k_prefix(const float* __restrict__ conv1_w) {
    int t = threadIdx.x;
    if (t >= 128) return;
    const float* w = conv1_w + t * 25;
    float P[6][6];
#pragma unroll
    for (int i = 0; i < 6; ++i) { P[0][i] = 0.f; P[i][0] = 0.f; }
#pragma unroll
    for (int j = 1; j <= 5; ++j)
#pragma unroll
        for (int i = 1; i <= 5; ++i)
            P[j][i] = w[(j-1)*5 + (i-1)] + P[j-1][i] + P[j][i-1] - P[j-1][i-1];
#pragma unroll
    for (int j = 0; j < 6; ++j)
#pragma unroll
        for (int i = 0; i < 6; ++i)
            g_P[t*36 + j*6 + i] = P[j][i];
}

// ---------------------------------------------------------------------------
// Kernel 2: sp + conv1 + bias + maxpool2 via per-axis clamp classes.
// The 5x5-window/rectangle intersection clamp (dlo,dhi) takes <=12 distinct
// values along each axis, so conv1(co,y,x) is piecewise constant on a class
// grid. Build T[ci][co][cy*nx+cx] once per block, then each pixel is lookups.
// ---------------------------------------------------------------------------
#define MAXCLS 16

struct SpShm {
    float sP[4608];        // [co*2+ci][36]
    float T[2][64*128];    // [ci][co][class]  (class stride 128)
    float sB[64];
    int   xcls[2][64], ycls[2][64];       // per-coordinate class id (60 used)
    int   xpl[2][MAXCLS], xph[2][MAXCLS]; // class -> (dlo, dhi)
    int   ypl[2][MAXCLS], yph[2][MAXCLS];
    int   nx[2], ny[2];
    int   rxlo[2], rxhi[2], rylo[2], ryhi[2];
};
#define SP_SMEM ((int)sizeof(SpShm))

__global__ void __launch_bounds__(256, 2)
k_sp_conv1(const float* __restrict__ bboxes,
           const int*   __restrict__ pairs,
           const float* __restrict__ conv1_b) {
    extern __shared__ char smraw[];
    SpShm* S = (SpShm*)smraw;

    int n = blockIdx.x, tid = threadIdx.x;
    for (int i = tid; i < 4608; i += 256) S->sP[i] = g_P[i];
    if (tid < 64) S->sB[tid] = conv1_b[tid];

    if (tid == 0) {
        int b = n >> 6, r = n & 63;
        int o0 = pairs[(b*64 + r)*2 + 0];
        int o1 = pairs[(b*64 + r)*2 + 1];
        const float* A  = bboxes + ((size_t)b*32 + o0)*4;
        const float* Bx = bboxes + ((size_t)b*32 + o1)*4;
        float ux1 = fminf(A[0], Bx[0]), uy1 = fminf(A[1], Bx[1]);
        float ux2 = fmaxf(A[2], Bx[2]), uy2 = fmaxf(A[3], Bx[3]);
        float uw = fmaxf(ux2 - ux1, 1e-6f), uh = fmaxf(uy2 - uy1, 1e-6f);
        const float* bx[2] = {A, Bx};
#pragma unroll
        for (int ci = 0; ci < 2; ++ci) {
            float x1 = (bx[ci][0] - ux1) / uw * 64.0f;
            float y1 = (bx[ci][1] - uy1) / uh * 64.0f;
            float x2 = (bx[ci][2] - ux1) / uw * 64.0f;
            float y2 = (bx[ci][3] - uy1) / uh * 64.0f;
            S->rxlo[ci] = max(0,  (int)ceilf (x1 - 0.5f));
            S->rxhi[ci] = min(63, (int)floorf(x2 - 0.5f));
            S->rylo[ci] = max(0,  (int)ceilf (y1 - 0.5f));
            S->ryhi[ci] = min(63, (int)floorf(y2 - 0.5f));
        }
    }
    __syncthreads();

    // Class dedup: 4 threads, one per (axis, ci).
    if (tid < 4) {
        int ci = tid >> 1, ax = tid & 1;
        int rlo = ax ? S->rylo[ci] : S->rxlo[ci];
        int rhi = ax ? S->ryhi[ci] : S->rxhi[ci];
        int* cls  = ax ? S->ycls[ci] : S->xcls[ci];
        int* lstL = ax ? S->ypl[ci]  : S->xpl[ci];
        int* lstH = ax ? S->yph[ci]  : S->xph[ci];
        int keys[MAXCLS];
        int nc = 0;
        for (int v = 0; v < 60; ++v) {
            int lo = max(0, rlo - v), hi = min(4, rhi - v);
            int key = (hi >= lo) ? (lo * 6 + hi) : 99;
            int id = -1;
            for (int j = 0; j < nc; ++j) if (keys[j] == key) { id = j; break; }
            if (id < 0) {
                id = nc;
                keys[nc] = key;
                lstL[nc] = (hi >= lo) ? lo : 1;   // invalid -> (1,0): hi<lo
                lstH[nc] = (hi >= lo) ? hi : 0;
                ++nc;
            }
            cls[v] = id;
        }
        if (ax) S->ny[ci] = nc; else S->nx[ci] = nc;
    }
    __syncthreads();

    // Build value tables T[ci][co][cy*nx+cx]
#pragma unroll
    for (int ci = 0; ci < 2; ++ci) {
        int nxv = S->nx[ci], nyv = S->ny[ci];
        int ncls = nxv * nyv;
        int tot = 64 * ncls;
        for (int i = tid; i < tot; i += 256) {
            int co = i / ncls, c = i - co * ncls;
            int cy = c / nxv,  cx = c - cy * nxv;
            int xl = S->xpl[ci][cx], xh = S->xph[ci][cx];
            int yl = S->ypl[ci][cy], yh = S->yph[ci][cy];
            float v = 0.f;
            if (xh >= xl && yh >= yl) {
                const float* P = S->sP + (co*2 + ci)*36;
                v = P[(yh+1)*6 + (xh+1)] - P[yl*6 + (xh+1)]
                  - P[(yh+1)*6 + xl]     + P[yl*6 + xl];
            }
            S->T[ci][co*128 + c] = v;
        }
    }
    __syncthreads();

    int nx0 = S->nx[0], nx1 = S->nx[1];
    for (int pix = tid; pix < 900; pix += 256) {
        int py = pix / 30, px = pix - py*30;
        int y = 2*py, x = 2*px;
        int c0[4], c1[4];
        {
            int a0 = S->ycls[0][y]*nx0, a1 = S->ycls[0][y+1]*nx0;
            int b0 = S->xcls[0][x],     b1 = S->xcls[0][x+1];
            c0[0] = a0+b0; c0[1] = a0+b1; c0[2] = a1+b0; c0[3] = a1+b1;
        }
        {
            int a0 = S->ycls[1][y]*nx1, a1 = S->ycls[1][y+1]*nx1;
            int b0 = S->xcls[1][x],     b1 = S->xcls[1][x+1];
            c1[0] = a0+b0; c1[1] = a0+b1; c1[2] = a1+b0; c1[3] = a1+b1;
        }
        float* outp = g_x1 + (size_t)n * X1_PER_PAIR + pix;
#pragma unroll 8
        for (int co = 0; co < 64; ++co) {
            const float* T0 = S->T[0] + co*128;
            const float* T1 = S->T[1] + co*128;
            float v0 = T0[c0[0]] + T1[c1[0]];
            float v1 = T0[c0[1]] + T1[c1[1]];
            float v2 = T0[c0[2]] + T1[c1[2]];
            float v3 = T0[c0[3]] + T1[c1[3]];
            float best = fmaxf(fmaxf(v0, v1), fmaxf(v2, v3));
            outp[co * 900] = best + S->sB[co];
        }
    }
}

// ---------------------------------------------------------------------------
// Kernel 3: conv2 + bias + maxpool2 + mean. One block per pair, 192 threads.
// Output grid padded 26x28. 364 f32x2 pixel-pairs ((y,x)&(y+13,x)); each of
// 182 active threads owns TWO pairs -> acc[32co][2] (128 regs). Per tap:
// 32 broadcast LDS.64 + 4 input LDS feed 64 FFMA2 -> fma-pipe-bound.
// ---------------------------------------------------------------------------
#define CI_CHUNK 16
#define W_ROW 34
#define SMEM_IN_BYTES   (CI_CHUNK * 900 * 4)          // 57600
#define SMEM_W_BYTES    (CI_CHUNK * 25 * W_ROW * 8)   // 108800
#define SMEM3_BYTES     (SMEM_IN_BYTES + SMEM_W_BYTES)

__global__ void __launch_bounds__(192, 1)
k_conv2(const float* __restrict__ conv2_w, const float* __restrict__ conv2_b) {
    extern __shared__ char smem[];
    float* s_in = (float*)smem;                   // [CI_CHUNK][900]
    u64*   s_w  = (u64*)(smem + SMEM_IN_BYTES);   // [CI_CHUNK*25][W_ROW] packed {w,w}

    int n = blockIdx.x, tid = threadIdx.x;
    bool active = tid < 182;
    int tt = active ? tid : 0;
    int q0 = tt, q1 = tt + 182;
    int y0 = q0 / 28, x0 = q0 - y0*28;            // y0 in [0,6]
    int y1 = q1 / 28, x1 = q1 - y1*28;            // y1 in [6,12]

    u64 acc[32][2];
#pragma unroll
    for (int co = 0; co < 32; ++co) { acc[co][0] = 0ull; acc[co][1] = 0ull; }

    const float4* gsrc_base = (const float4*)(g_x1 + (size_t)n * X1_PER_PAIR);

    for (int ci0 = 0; ci0 < 64; ci0 += CI_CHUNK) {
        __syncthreads();
        {   // input chunk (vectorized, contiguous)
            const float4* src = gsrc_base + (ci0 * 900) / 4;
            float4* dst = (float4*)s_in;
            for (int i = tid; i < (CI_CHUNK * 900) / 4; i += 192) dst[i] = src[i];
        }
        {   // weight chunk, pre-packed {w,w}
            for (int i = tid; i < 32 * CI_CHUNK * 25; i += 192) {
                int co  = i / (CI_CHUNK * 25);
                int rem = i - co * (CI_CHUNK * 25);
                int cil = rem / 25;
                int k   = rem - cil * 25;
                float w = conv2_w[co * 1600 + (ci0 + cil) * 25 + k];
                s_w[(cil * 25 + k) * W_ROW + co] = pack2(w, w);
            }
        }
        __syncthreads();

        for (int cil = 0; cil < CI_CHUNK; ++cil) {
            const float* ib = s_in + cil * 900;
            const u64*   wb = s_w + cil * 25 * W_ROW;
#pragma unroll 1
            for (int dy = 0; dy < 5; ++dy) {
                const float* rA = ib + (y0 + dy)      * 30 + x0;
                const float* rB = ib + (y0 + 13 + dy) * 30 + x0;
                const float* rC = ib + (y1 + dy)      * 30 + x1;
                const float* rD = ib + (y1 + 13 + dy) * 30 + x1;
#pragma unroll
                for (int dx = 0; dx < 5; ++dx) {
                    u64 inA = pack2(rA[dx], rB[dx]);
                    u64 inB = pack2(rC[dx], rD[dx]);
                    const u64* wp = wb + (dy * 5 + dx) * W_ROW;
#pragma unroll
                    for (int co = 0; co < 32; ++co) {
                        u64 w2 = wp[co];
                        fma2(acc[co][0], w2, inA);
                        fma2(acc[co][1], w2, inB);
                    }
                }
            }
        }
    }
    __syncthreads();

    // Epilogue: stage, maxpool 26->13, mean, +bias.
    float* s_out  = (float*)smem;                     // [32][26][28]
    float* s_pool = (float*)(smem + 32*728*4);        // [32][169]
    if (active) {
#pragma unroll
        for (int co = 0; co < 32; ++co) {
            float a, b; unpack2(a, b, acc[co][0]);
            s_out[co*728 + y0*28 + x0]        = a;
            s_out[co*728 + (y0+13)*28 + x0]   = b;
            unpack2(a, b, acc[co][1]);
            s_out[co*728 + y1*28 + x1]        = a;
            s_out[co*728 + (y1+13)*28 + x1]   = b;
        }
    }
    __syncthreads();
    for (int idx = tid; idx < 32 * 169; idx += 192) {
        int co = idx / 169, q = idx - co * 169;
        int qy = q / 13, qx = q - qy * 13;
        const float* o = s_out + co*728 + qy*56 + qx*2;
        s_pool[idx] = fmaxf(fmaxf(o[0], o[1]), fmaxf(o[28], o[29]));
    }
    __syncthreads();
    if (tid < 32) {
        const float* pp = s_pool + tid * 169;
        float s = 0.f;
#pragma unroll 13
        for (int q = 0; q < 169; ++q) s += pp[q];
        g_feat[n * 32 + tid] = s * (1.0f / 169.0f) + conv2_b[tid];
    }
}

// ---------------------------------------------------------------------------
// Kernel 4: fc (32->512) + relu, 8 pairs per block (weight rows in registers).
// ---------------------------------------------------------------------------
__global__ void __launch_bounds__(512)
k_fc(const float* __restrict__ fc_w, const float* __restrict__ fc_b,
     float* __restrict__ out) {
    __shared__ float sf[8][32];
    int nb = blockIdx.x * 8, tid = threadIdx.x;
    if (tid < 256) {
        int j = tid >> 5, k = tid & 31;
        sf[j][k] = g_feat[(nb + j) * 32 + k];
    }
    __syncthreads();
    float w[32];
    const float* wr = fc_w + tid * 32;
#pragma unroll
    for (int k = 0; k < 32; ++k) w[k] = wr[k];
    float b = fc_b[tid];
#pragma unroll
    for (int j = 0; j < 8; ++j) {
        float s = b;
#pragma unroll
        for (int k = 0; k < 32; ++k) s += sf[j][k] * w[k];
        out[(size_t)(nb + j) * 512 + tid] = fmaxf(s, 0.f);
    }
}

// ---------------------------------------------------------------------------
extern "C" void kernel_launch(void* const* d_in, const int* in_sizes, int n_in,
                              void* d_out, int out_size) {
    const float* bboxes  = (const float*)d_in[0];
    const int*   pairs   = (const int*)  d_in[3];
    const float* conv1_w = (const float*)d_in[4];
    const float* conv1_b = (const float*)d_in[5];
    const float* conv2_w = (const float*)d_in[6];
    const float* conv2_b = (const float*)d_in[7];
    const float* fc_w    = (const float*)d_in[8];
    const float* fc_b    = (const float*)d_in[9];
    float* out = (float*)d_out;

    cudaFuncSetAttribute(k_sp_conv1, cudaFuncAttributeMaxDynamicSharedMemorySize, SP_SMEM);
    cudaFuncSetAttribute(k_conv2, cudaFuncAttributeMaxDynamicSharedMemorySize, SMEM3_BYTES);

    k_prefix  <<<1, 128>>>(conv1_w);
    k_sp_conv1<<<NPAIR, 256, SP_SMEM>>>(bboxes, pairs, conv1_b);
    k_conv2   <<<NPAIR, 192, SMEM3_BYTES>>>(conv2_w, conv2_b);
    k_fc      <<<NPAIR/8, 512>>>(fc_w, fc_b, out);
}